// round 13
// baseline (speedup 1.0000x reference)
#include <cuda_runtime.h>
#include <math.h>
#include <cstdint>

// RNNLayer_73074573574765: delayed RNN. B=64,S=512,I=H=1024,DELAY=4.
// Phase 1: pre = X.Wih^T + bih + bhh  (R11-proven mma.sync tf32 + ldmatrix)
// Phase 2: persistent mma.sync tf32; B fragments loaded DIRECTLY from
//          pre-split global (no SMEM/ldmatrix for B), A via SMEM+ldmatrix
//          with in-kernel split; 3 independent accumulators; grid barrier.

namespace {
constexpr int Bz = 64;
constexpr int Sz = 512;
constexpr int Iz = 1024;
constexpr int Hz = 1024;
constexpr int DZ = 4;
constexpr int NBLK = 128;
constexpr int NGROUP = Sz / DZ;  // 128
}  // namespace

__device__ float g_pre[(size_t)Bz * Sz * Hz];
// pre-split recurrent weights (tf32 hi/lo bit patterns)
__device__ uint32_t g_WhhH[(size_t)Hz * Hz];
__device__ uint32_t g_WhhL[(size_t)Hz * Hz];
__device__ unsigned g_cnt;  // zero-init; self-cleaning
__device__ unsigned g_gen;  // monotonic; equality-compared (replay-safe)

// ---------------- PTX helpers (base-target legal) ----------------
__device__ __forceinline__ uint32_t cvt_tf32(float f) {
  uint32_t r;
  asm("cvt.rna.tf32.f32 %0, %1;" : "=r"(r) : "f"(f));
  return r;
}
__device__ __forceinline__ void mma_tf32(float* c, uint32_t a0, uint32_t a1,
                                         uint32_t a2, uint32_t a3, uint32_t b0,
                                         uint32_t b1) {
  asm volatile(
      "mma.sync.aligned.m16n8k8.row.col.f32.tf32.tf32.f32 "
      "{%0,%1,%2,%3}, {%4,%5,%6,%7}, {%8,%9}, {%0,%1,%2,%3};"
      : "+f"(c[0]), "+f"(c[1]), "+f"(c[2]), "+f"(c[3])
      : "r"(a0), "r"(a1), "r"(a2), "r"(a3), "r"(b0), "r"(b1));
}
__device__ __forceinline__ void split_tf32(float x, uint32_t& hi,
                                           uint32_t& lo) {
  hi = cvt_tf32(x);
  lo = cvt_tf32(x - __uint_as_float(hi));
}
__device__ __forceinline__ void split4(float4 v, uint4& h, uint4& l) {
  split_tf32(v.x, h.x, l.x);
  split_tf32(v.y, h.y, l.y);
  split_tf32(v.z, h.z, l.z);
  split_tf32(v.w, h.w, l.w);
}
__device__ __forceinline__ uint32_t smem_u32(const void* p) {
  uint32_t a;
  asm("{ .reg .u64 t; cvta.to.shared.u64 t, %1; cvt.u32.u64 %0, t; }"
      : "=r"(a) : "l"(p));
  return a;
}
__device__ __forceinline__ void ldsm4(uint32_t& r0, uint32_t& r1, uint32_t& r2,
                                      uint32_t& r3, uint32_t addr) {
  asm volatile(
      "ldmatrix.sync.aligned.m8n8.x4.shared.b16 {%0,%1,%2,%3}, [%4];"
      : "=r"(r0), "=r"(r1), "=r"(r2), "=r"(r3)
      : "r"(addr));
}

// ---------------------------------------------------------------------------
// One-time weight split kernel
// ---------------------------------------------------------------------------
__global__ void split_w_kernel(const float* __restrict__ W) {
  const int idx = blockIdx.x * 256 + threadIdx.x;  // 262144 float4s
  float4 v = *reinterpret_cast<const float4*>(W + (size_t)idx * 4);
  uint4 h, l;
  split4(v, h, l);
  *reinterpret_cast<uint4*>(&g_WhhH[(size_t)idx * 4]) = h;
  *reinterpret_cast<uint4*>(&g_WhhL[(size_t)idx * 4]) = l;
}

// ---------------------------------------------------------------------------
// Phase 1 (R11 exact): pre[m,n] = sum_k X[m,k]*Wih[n,k] + bih[n]+bhh[n]
// ---------------------------------------------------------------------------
__global__ __launch_bounds__(256) void pre_gemm_mma(
    const float* __restrict__ X, const float* __restrict__ Wih,
    const float* __restrict__ bih, const float* __restrict__ bhh) {
  __shared__ __align__(16) uint32_t Ah[128][20];
  __shared__ __align__(16) uint32_t Al[128][20];
  __shared__ __align__(16) uint32_t Bh[128][20];
  __shared__ __align__(16) uint32_t Bl[128][20];

  const int tid = threadIdx.x;
  const int bn = blockIdx.x;
  const int bm = blockIdx.y;
  const int w = tid >> 5;
  const int lane = tid & 31;
  const int gid = lane >> 2;
  const int tig = lane & 3;
  const int wm = w >> 2;
  const int wn = w & 3;

  const int r0 = tid >> 2;
  const int r1 = r0 + 64;
  const int q = tid & 3;
  const float* Abase = X + (size_t)(bm * 128) * Iz;
  const float* Bbase = Wih + (size_t)(bn * 128) * Iz;

  const int rowL = lane & 15;
  const int kL = (lane >> 4) * 4;
  const uint32_t aS = smem_u32(Ah), alS = smem_u32(Al);
  const uint32_t bS = smem_u32(Bh), blS = smem_u32(Bl);
  const uint32_t aoff = ((uint32_t)((wm * 64 + rowL) * 20 + kL)) * 4;
  const uint32_t boff = ((uint32_t)((wn * 32 + rowL) * 20 + kL)) * 4;

  float c[4][4][4];
#pragma unroll
  for (int i = 0; i < 4; i++)
#pragma unroll
    for (int j = 0; j < 4; j++)
#pragma unroll
      for (int e = 0; e < 4; e++) c[i][j][e] = 0.f;

  float4 pa0, pa1, pb0, pb1;
  pa0 = *reinterpret_cast<const float4*>(Abase + (size_t)r0 * Iz + q * 4);
  pa1 = *reinterpret_cast<const float4*>(Abase + (size_t)r1 * Iz + q * 4);
  pb0 = *reinterpret_cast<const float4*>(Bbase + (size_t)r0 * Iz + q * 4);
  pb1 = *reinterpret_cast<const float4*>(Bbase + (size_t)r1 * Iz + q * 4);

  const int NCH = Iz / 16;  // 64
  for (int ch = 0; ch < NCH; ++ch) {
    {
      uint4 h, l;
      split4(pa0, h, l);
      *reinterpret_cast<uint4*>(&Ah[r0][q * 4]) = h;
      *reinterpret_cast<uint4*>(&Al[r0][q * 4]) = l;
      split4(pa1, h, l);
      *reinterpret_cast<uint4*>(&Ah[r1][q * 4]) = h;
      *reinterpret_cast<uint4*>(&Al[r1][q * 4]) = l;
      split4(pb0, h, l);
      *reinterpret_cast<uint4*>(&Bh[r0][q * 4]) = h;
      *reinterpret_cast<uint4*>(&Bl[r0][q * 4]) = l;
      split4(pb1, h, l);
      *reinterpret_cast<uint4*>(&Bh[r1][q * 4]) = h;
      *reinterpret_cast<uint4*>(&Bl[r1][q * 4]) = l;
    }
    __syncthreads();

    if (ch + 1 < NCH) {
      const size_t ko = (size_t)(ch + 1) * 16 + q * 4;
      pa0 = *reinterpret_cast<const float4*>(Abase + (size_t)r0 * Iz + ko);
      pa1 = *reinterpret_cast<const float4*>(Abase + (size_t)r1 * Iz + ko);
      pb0 = *reinterpret_cast<const float4*>(Bbase + (size_t)r0 * Iz + ko);
      pb1 = *reinterpret_cast<const float4*>(Bbase + (size_t)r1 * Iz + ko);
    }

#pragma unroll
    for (int ks = 0; ks < 2; ++ks) {
      const uint32_t kb = ks * 32;
      uint32_t ah[4][4], al[4][4];
#pragma unroll
      for (int mt = 0; mt < 4; ++mt) {
        ldsm4(ah[mt][0], ah[mt][1], ah[mt][2], ah[mt][3],
              aS + aoff + mt * (16 * 20 * 4) + kb);
        ldsm4(al[mt][0], al[mt][1], al[mt][2], al[mt][3],
              alS + aoff + mt * (16 * 20 * 4) + kb);
      }
      uint32_t bh[2][4], bl[2][4];
#pragma unroll
      for (int p = 0; p < 2; ++p) {
        ldsm4(bh[p][0], bh[p][1], bh[p][2], bh[p][3],
              bS + boff + p * (16 * 20 * 4) + kb);
        ldsm4(bl[p][0], bl[p][1], bl[p][2], bl[p][3],
              blS + boff + p * (16 * 20 * 4) + kb);
      }
#pragma unroll
      for (int mt = 0; mt < 4; ++mt)
#pragma unroll
        for (int nt = 0; nt < 4; ++nt) {
          const int p = nt >> 1, o = nt & 1;
          mma_tf32(c[mt][nt], ah[mt][0], ah[mt][1], ah[mt][2], ah[mt][3],
                   bl[p][o], bl[p][o + 2]);
          mma_tf32(c[mt][nt], al[mt][0], al[mt][1], al[mt][2], al[mt][3],
                   bh[p][o], bh[p][o + 2]);
          mma_tf32(c[mt][nt], ah[mt][0], ah[mt][1], ah[mt][2], ah[mt][3],
                   bh[p][o], bh[p][o + 2]);
        }
    }
    __syncthreads();
  }

#pragma unroll
  for (int nt = 0; nt < 4; ++nt) {
    const int n = bn * 128 + wn * 32 + nt * 8 + 2 * tig;
    const float bx = bih[n] + bhh[n];
    const float by = bih[n + 1] + bhh[n + 1];
#pragma unroll
    for (int mt = 0; mt < 4; ++mt) {
      const int m = bm * 128 + wm * 64 + mt * 16 + gid;
      float2 v0 = make_float2(c[mt][nt][0] + bx, c[mt][nt][1] + by);
      float2 v1 = make_float2(c[mt][nt][2] + bx, c[mt][nt][3] + by);
      *reinterpret_cast<float2*>(&g_pre[(size_t)m * Hz + n]) = v0;
      *reinterpret_cast<float2*>(&g_pre[(size_t)(m + 8) * Hz + n]) = v1;
    }
  }
}

// ---------------------------------------------------------------------------
// grid barrier (R3-proven)
// ---------------------------------------------------------------------------
__device__ __forceinline__ void grid_barrier() {
  __syncthreads();
  if (threadIdx.x == 0) {
    unsigned gen = *(volatile unsigned*)&g_gen;
    __threadfence();
    if (atomicAdd(&g_cnt, 1) == NBLK - 1) {
      g_cnt = 0;
      __threadfence();
      atomicAdd(&g_gen, 1);
    } else {
      while (*(volatile unsigned*)&g_gen == gen) __nanosleep(32);
    }
    __threadfence();
  }
  __syncthreads();
}

// ---------------------------------------------------------------------------
// Phase 2: persistent mma.sync tf32, B direct-from-global registers.
// 128 blocks x 256 thr. Block tile 32m x 64n (grid 8 x 16).
// Warps 2m x 4n; warp tile 16m x 16n. A: SMEM+ldmatrix, in-kernel split.
// B: per-lane LDGs from g_WhhH/L, 4-slot depth-2 register pipeline.
// 3 independent accumulators (hh, lh, hl).
// ---------------------------------------------------------------------------
__global__ __launch_bounds__(256, 1) void rnn_persistent_mma(
    const float* __restrict__ hs, float* __restrict__ out,
    float* __restrict__ hf) {
  __shared__ __align__(16) uint32_t Ah[32][68], Al[32][68];

  const int tid = threadIdx.x;
  const int bmi = blockIdx.x >> 4;  // 0..7  over M=256
  const int bni = blockIdx.x & 15;  // 0..15 over N=1024

  const int w = tid >> 5;
  const int lane = tid & 31;
  const int gid = lane >> 2;
  const int tig = lane & 3;
  const int wm = w >> 2;  // 0..1
  const int wn = w & 3;   // 0..3

  // A loader: tile row arow (0..31), k-quad pair akq (quads akq, akq+8)
  const int arow = tid >> 3;
  const int akq = tid & 7;
  const int m_abs_l = bmi * 32 + arow;
  const int dl = m_abs_l >> 6;
  const int bl_ = m_abs_l & 63;

  // B per-lane row pointers (pre-split global)
  const int n_a = bni * 64 + wn * 16 + gid;
  const uint32_t* pHa = g_WhhH + (size_t)n_a * Hz;
  const uint32_t* pHb = pHa + (size_t)8 * Hz;
  const uint32_t* pLa = g_WhhL + (size_t)n_a * Hz;
  const uint32_t* pLb = pLa + (size_t)8 * Hz;

  // ldmatrix lane addressing for A
  const int rowL = lane & 15;
  const int kL = (lane >> 4) * 4;
  const uint32_t aHS =
      smem_u32(Ah) + ((uint32_t)((wm * 16 + rowL) * 68 + kL)) * 4;
  const uint32_t aLS =
      smem_u32(Al) + ((uint32_t)((wm * 16 + rowL) * 68 + kL)) * 4;

  for (int g = 0; g < NGROUP; ++g) {
    const float* Arow =
        (g == 0) ? hs + (size_t)m_abs_l * Hz
                 : out + ((size_t)bl_ * Sz + (4 * g + dl - 4)) * Hz;

    float chh[2][4], clh[2][4], chl[2][4];
#pragma unroll
    for (int nt = 0; nt < 2; ++nt)
#pragma unroll
      for (int e = 0; e < 4; ++e) {
        chh[nt][e] = 0.f;
        clh[nt][e] = 0.f;
        chl[nt][e] = 0.f;
      }

    // B register pipeline: 4 slots, depth-2 prefetch. Slot layout:
    //  bh[s] = {Wh[n_a][k+tig], Wh[n_a+8][k+tig], Wh[n_a][k+tig+4], Wh[n_a+8][k+tig+4]}
    uint32_t bhq[4][4], blq[4][4];
#pragma unroll
    for (int s = 0; s < 2; ++s) {
      const int kk = s * 8;
      bhq[s][0] = pHa[kk + tig];
      bhq[s][1] = pHb[kk + tig];
      bhq[s][2] = pHa[kk + tig + 4];
      bhq[s][3] = pHb[kk + tig + 4];
      blq[s][0] = pLa[kk + tig];
      blq[s][1] = pLb[kk + tig];
      blq[s][2] = pLa[kk + tig + 4];
      blq[s][3] = pLb[kk + tig + 4];
    }

    // prefetch A chunk 0
    float4 pa0 = *reinterpret_cast<const float4*>(Arow + akq * 4);
    float4 pa1 = *reinterpret_cast<const float4*>(Arow + (akq + 8) * 4);

    const int NCH = Hz / 64;  // 16
    for (int ch = 0; ch < NCH; ++ch) {
      {
        uint4 h, l;
        split4(pa0, h, l);
        *reinterpret_cast<uint4*>(&Ah[arow][akq * 4]) = h;
        *reinterpret_cast<uint4*>(&Al[arow][akq * 4]) = l;
        split4(pa1, h, l);
        *reinterpret_cast<uint4*>(&Ah[arow][(akq + 8) * 4]) = h;
        *reinterpret_cast<uint4*>(&Al[arow][(akq + 8) * 4]) = l;
      }
      __syncthreads();

      if (ch + 1 < NCH) {
        const int ko = (ch + 1) * 64;
        pa0 = *reinterpret_cast<const float4*>(Arow + ko + akq * 4);
        pa1 = *reinterpret_cast<const float4*>(Arow + ko + (akq + 8) * 4);
      }

#pragma unroll
      for (int ks = 0; ks < 8; ++ks) {
        const int t = ch * 8 + ks;
        // prefetch B for step t+2
        if (t + 2 < 128) {
          const int kk = (t + 2) * 8;
          const int s = (t + 2) & 3;
          bhq[s][0] = pHa[kk + tig];
          bhq[s][1] = pHb[kk + tig];
          bhq[s][2] = pHa[kk + tig + 4];
          bhq[s][3] = pHb[kk + tig + 4];
          blq[s][0] = pLa[kk + tig];
          blq[s][1] = pLb[kk + tig];
          blq[s][2] = pLa[kk + tig + 4];
          blq[s][3] = pLb[kk + tig + 4];
        }
        // A fragments for this k-step
        uint32_t ah0, ah1, ah2, ah3, al0, al1, al2, al3;
        ldsm4(ah0, ah1, ah2, ah3, aHS + ks * 32);
        ldsm4(al0, al1, al2, al3, aLS + ks * 32);
        const int cs = t & 3;
        // 6 independent chains
        mma_tf32(chh[0], ah0, ah1, ah2, ah3, bhq[cs][0], bhq[cs][2]);
        mma_tf32(chh[1], ah0, ah1, ah2, ah3, bhq[cs][1], bhq[cs][3]);
        mma_tf32(clh[0], al0, al1, al2, al3, bhq[cs][0], bhq[cs][2]);
        mma_tf32(clh[1], al0, al1, al2, al3, bhq[cs][1], bhq[cs][3]);
        mma_tf32(chl[0], ah0, ah1, ah2, ah3, blq[cs][0], blq[cs][2]);
        mma_tf32(chl[1], ah0, ah1, ah2, ah3, blq[cs][1], blq[cs][3]);
      }
      __syncthreads();
    }

    // epilogue: tanh(pre + sum) -> out (+ h_final on last group)
#pragma unroll
    for (int nt = 0; nt < 2; ++nt) {
      const int n = bni * 64 + wn * 16 + nt * 8 + 2 * tig;
#pragma unroll
      for (int half = 0; half < 2; ++half) {
        const int m_abs = bmi * 32 + wm * 16 + gid + half * 8;
        const int d = m_abs >> 6;
        const int b = m_abs & 63;
        const size_t base = ((size_t)b * Sz + (4 * g + d)) * Hz + n;
        float2 pv = *reinterpret_cast<const float2*>(&g_pre[base]);
        const int e = half * 2;
        float sx = chh[nt][e] + (clh[nt][e] + chl[nt][e]);
        float sy = chh[nt][e + 1] + (clh[nt][e + 1] + chl[nt][e + 1]);
        float2 ov = make_float2(tanhf(pv.x + sx), tanhf(pv.y + sy));
        *reinterpret_cast<float2*>(&out[base]) = ov;
        if (g == NGROUP - 1) {
          *reinterpret_cast<float2*>(&hf[((size_t)d * Bz + b) * Hz + n]) = ov;
        }
      }
    }
    grid_barrier();
  }
}

extern "C" void kernel_launch(void* const* d_in, const int* in_sizes, int n_in,
                              void* d_out, int out_size) {
  (void)in_sizes;
  (void)n_in;
  (void)out_size;
  const float* X = (const float*)d_in[0];    // [B,S,I]
  const float* hs = (const float*)d_in[1];   // [4,B,H]
  const float* Wih = (const float*)d_in[2];  // [H,I]
  const float* Whh = (const float*)d_in[3];  // [H,H]
  const float* bih = (const float*)d_in[4];  // [H]
  const float* bhh = (const float*)d_in[5];  // [H]

  float* out = (float*)d_out;              // [B,S,H]
  float* hf = out + (size_t)Bz * Sz * Hz;  // [4,B,H]

  split_w_kernel<<<1024, 256>>>(Whh);
  pre_gemm_mma<<<dim3(Hz / 128, (Bz * Sz) / 128), 256>>>(X, Wih, bih, bhh);

  rnn_persistent_mma<<<NBLK, 256>>>(hs, out, hf);
}

// round 16
// speedup vs baseline: 1.6313x; 1.6313x over previous
#include <cuda_runtime.h>
#include <math.h>
#include <cstdint>

// RNNLayer_73074573574765: delayed RNN. B=64,S=512,I=H=1024,DELAY=4.
// Phase 1: pre = X.Wih^T + bih + bhh  (R11-proven mma.sync tf32 + ldmatrix)
// Phase 2: R11 persistent kernel with 3 INDEPENDENT accumulator chains
//          (hh, lh, hl) instead of one serial 3-pass chain. Grid barrier.

namespace {
constexpr int Bz = 64;
constexpr int Sz = 512;
constexpr int Iz = 1024;
constexpr int Hz = 1024;
constexpr int DZ = 4;
constexpr int NBLK = 128;
constexpr int NGROUP = Sz / DZ;  // 128
}  // namespace

__device__ float g_pre[(size_t)Bz * Sz * Hz];
__device__ unsigned g_cnt;  // zero-init; self-cleaning
__device__ unsigned g_gen;  // monotonic; equality-compared (replay-safe)

// ---------------- PTX helpers (base-target legal) ----------------
__device__ __forceinline__ uint32_t cvt_tf32(float f) {
  uint32_t r;
  asm("cvt.rna.tf32.f32 %0, %1;" : "=r"(r) : "f"(f));
  return r;
}
__device__ __forceinline__ void mma_tf32(float* c, uint32_t a0, uint32_t a1,
                                         uint32_t a2, uint32_t a3, uint32_t b0,
                                         uint32_t b1) {
  asm volatile(
      "mma.sync.aligned.m16n8k8.row.col.f32.tf32.tf32.f32 "
      "{%0,%1,%2,%3}, {%4,%5,%6,%7}, {%8,%9}, {%0,%1,%2,%3};"
      : "+f"(c[0]), "+f"(c[1]), "+f"(c[2]), "+f"(c[3])
      : "r"(a0), "r"(a1), "r"(a2), "r"(a3), "r"(b0), "r"(b1));
}
__device__ __forceinline__ void split_tf32(float x, uint32_t& hi,
                                           uint32_t& lo) {
  hi = cvt_tf32(x);
  lo = cvt_tf32(x - __uint_as_float(hi));
}
__device__ __forceinline__ void split4(float4 v, uint4& h, uint4& l) {
  split_tf32(v.x, h.x, l.x);
  split_tf32(v.y, h.y, l.y);
  split_tf32(v.z, h.z, l.z);
  split_tf32(v.w, h.w, l.w);
}
__device__ __forceinline__ uint32_t smem_u32(const void* p) {
  uint32_t a;
  asm("{ .reg .u64 t; cvta.to.shared.u64 t, %1; cvt.u32.u64 %0, t; }"
      : "=r"(a) : "l"(p));
  return a;
}
__device__ __forceinline__ void ldsm4(uint32_t& r0, uint32_t& r1, uint32_t& r2,
                                      uint32_t& r3, uint32_t addr) {
  asm volatile(
      "ldmatrix.sync.aligned.m8n8.x4.shared.b16 {%0,%1,%2,%3}, [%4];"
      : "=r"(r0), "=r"(r1), "=r"(r2), "=r"(r3)
      : "r"(addr));
}

// ---------------------------------------------------------------------------
// Phase 1 (R11 exact): pre[m,n] = sum_k X[m,k]*Wih[n,k] + bih[n]+bhh[n]
// ---------------------------------------------------------------------------
__global__ __launch_bounds__(256) void pre_gemm_mma(
    const float* __restrict__ X, const float* __restrict__ Wih,
    const float* __restrict__ bih, const float* __restrict__ bhh) {
  __shared__ __align__(16) uint32_t Ah[128][20];
  __shared__ __align__(16) uint32_t Al[128][20];
  __shared__ __align__(16) uint32_t Bh[128][20];
  __shared__ __align__(16) uint32_t Bl[128][20];

  const int tid = threadIdx.x;
  const int bn = blockIdx.x;
  const int bm = blockIdx.y;
  const int w = tid >> 5;
  const int lane = tid & 31;
  const int gid = lane >> 2;
  const int tig = lane & 3;
  const int wm = w >> 2;
  const int wn = w & 3;

  const int r0 = tid >> 2;
  const int r1 = r0 + 64;
  const int q = tid & 3;
  const float* Abase = X + (size_t)(bm * 128) * Iz;
  const float* Bbase = Wih + (size_t)(bn * 128) * Iz;

  const int rowL = lane & 15;
  const int kL = (lane >> 4) * 4;
  const uint32_t aS = smem_u32(Ah), alS = smem_u32(Al);
  const uint32_t bS = smem_u32(Bh), blS = smem_u32(Bl);
  const uint32_t aoff = ((uint32_t)((wm * 64 + rowL) * 20 + kL)) * 4;
  const uint32_t boff = ((uint32_t)((wn * 32 + rowL) * 20 + kL)) * 4;

  float c[4][4][4];
#pragma unroll
  for (int i = 0; i < 4; i++)
#pragma unroll
    for (int j = 0; j < 4; j++)
#pragma unroll
      for (int e = 0; e < 4; e++) c[i][j][e] = 0.f;

  float4 pa0, pa1, pb0, pb1;
  pa0 = *reinterpret_cast<const float4*>(Abase + (size_t)r0 * Iz + q * 4);
  pa1 = *reinterpret_cast<const float4*>(Abase + (size_t)r1 * Iz + q * 4);
  pb0 = *reinterpret_cast<const float4*>(Bbase + (size_t)r0 * Iz + q * 4);
  pb1 = *reinterpret_cast<const float4*>(Bbase + (size_t)r1 * Iz + q * 4);

  const int NCH = Iz / 16;  // 64
  for (int ch = 0; ch < NCH; ++ch) {
    {
      uint4 h, l;
      split4(pa0, h, l);
      *reinterpret_cast<uint4*>(&Ah[r0][q * 4]) = h;
      *reinterpret_cast<uint4*>(&Al[r0][q * 4]) = l;
      split4(pa1, h, l);
      *reinterpret_cast<uint4*>(&Ah[r1][q * 4]) = h;
      *reinterpret_cast<uint4*>(&Al[r1][q * 4]) = l;
      split4(pb0, h, l);
      *reinterpret_cast<uint4*>(&Bh[r0][q * 4]) = h;
      *reinterpret_cast<uint4*>(&Bl[r0][q * 4]) = l;
      split4(pb1, h, l);
      *reinterpret_cast<uint4*>(&Bh[r1][q * 4]) = h;
      *reinterpret_cast<uint4*>(&Bl[r1][q * 4]) = l;
    }
    __syncthreads();

    if (ch + 1 < NCH) {
      const size_t ko = (size_t)(ch + 1) * 16 + q * 4;
      pa0 = *reinterpret_cast<const float4*>(Abase + (size_t)r0 * Iz + ko);
      pa1 = *reinterpret_cast<const float4*>(Abase + (size_t)r1 * Iz + ko);
      pb0 = *reinterpret_cast<const float4*>(Bbase + (size_t)r0 * Iz + ko);
      pb1 = *reinterpret_cast<const float4*>(Bbase + (size_t)r1 * Iz + ko);
    }

#pragma unroll
    for (int ks = 0; ks < 2; ++ks) {
      const uint32_t kb = ks * 32;
      uint32_t ah[4][4], al[4][4];
#pragma unroll
      for (int mt = 0; mt < 4; ++mt) {
        ldsm4(ah[mt][0], ah[mt][1], ah[mt][2], ah[mt][3],
              aS + aoff + mt * (16 * 20 * 4) + kb);
        ldsm4(al[mt][0], al[mt][1], al[mt][2], al[mt][3],
              alS + aoff + mt * (16 * 20 * 4) + kb);
      }
      uint32_t bh[2][4], bl[2][4];
#pragma unroll
      for (int p = 0; p < 2; ++p) {
        ldsm4(bh[p][0], bh[p][1], bh[p][2], bh[p][3],
              bS + boff + p * (16 * 20 * 4) + kb);
        ldsm4(bl[p][0], bl[p][1], bl[p][2], bl[p][3],
              blS + boff + p * (16 * 20 * 4) + kb);
      }
#pragma unroll
      for (int mt = 0; mt < 4; ++mt)
#pragma unroll
        for (int nt = 0; nt < 4; ++nt) {
          const int p = nt >> 1, o = nt & 1;
          mma_tf32(c[mt][nt], ah[mt][0], ah[mt][1], ah[mt][2], ah[mt][3],
                   bl[p][o], bl[p][o + 2]);
          mma_tf32(c[mt][nt], al[mt][0], al[mt][1], al[mt][2], al[mt][3],
                   bh[p][o], bh[p][o + 2]);
          mma_tf32(c[mt][nt], ah[mt][0], ah[mt][1], ah[mt][2], ah[mt][3],
                   bh[p][o], bh[p][o + 2]);
        }
    }
    __syncthreads();
  }

#pragma unroll
  for (int nt = 0; nt < 4; ++nt) {
    const int n = bn * 128 + wn * 32 + nt * 8 + 2 * tig;
    const float bx = bih[n] + bhh[n];
    const float by = bih[n + 1] + bhh[n + 1];
#pragma unroll
    for (int mt = 0; mt < 4; ++mt) {
      const int m = bm * 128 + wm * 64 + mt * 16 + gid;
      float2 v0 = make_float2(c[mt][nt][0] + bx, c[mt][nt][1] + by);
      float2 v1 = make_float2(c[mt][nt][2] + bx, c[mt][nt][3] + by);
      *reinterpret_cast<float2*>(&g_pre[(size_t)m * Hz + n]) = v0;
      *reinterpret_cast<float2*>(&g_pre[(size_t)(m + 8) * Hz + n]) = v1;
    }
  }
}

// ---------------------------------------------------------------------------
// grid barrier (R3-proven)
// ---------------------------------------------------------------------------
__device__ __forceinline__ void grid_barrier() {
  __syncthreads();
  if (threadIdx.x == 0) {
    unsigned gen = *(volatile unsigned*)&g_gen;
    __threadfence();
    if (atomicAdd(&g_cnt, 1) == NBLK - 1) {
      g_cnt = 0;
      __threadfence();
      atomicAdd(&g_gen, 1);
    } else {
      while (*(volatile unsigned*)&g_gen == gen) __nanosleep(32);
    }
    __threadfence();
  }
  __syncthreads();
}

// ---------------------------------------------------------------------------
// Phase 2: persistent mma.sync tf32 kernel (R11 structure), but with
// 3 INDEPENDENT accumulator chains per ntile (hh, lh, hl) -> chain length
// drops 384 -> 128, un-exposing HMMA latency. Epilogue sums the chains.
// 128 blocks x 256 thr. Block tile 32m x 64n (grid 8 x 16). BK=64 (16/group).
// ---------------------------------------------------------------------------
__global__ __launch_bounds__(256, 1) void rnn_persistent_mma(
    const float* __restrict__ hs, const float* __restrict__ Whh,
    float* __restrict__ out, float* __restrict__ hf) {
  __shared__ __align__(16) uint32_t Ah[32][68], Al[32][68];
  __shared__ __align__(16) uint32_t Bh[64][68], Bl[64][68];

  const int tid = threadIdx.x;
  const int bmi = blockIdx.x >> 4;  // 0..7  over M=256
  const int bni = blockIdx.x & 15;  // 0..15 over N=1024

  const int w = tid >> 5;
  const int lane = tid & 31;
  const int gid = lane >> 2;
  const int tig = lane & 3;
  const int wm = w >> 2;  // 0..1
  const int wn = w & 3;   // 0..3

  // A loader: tile row arow (0..31), k-quad pair akq (quads akq, akq+8)
  const int arow = tid >> 3;
  const int akq = tid & 7;
  const int m_abs_l = bmi * 32 + arow;
  const int dl = m_abs_l >> 6;
  const int bl_ = m_abs_l & 63;
  // B loader: tile row brow (0..63), quads bkq+4j
  const int brow = tid >> 2;
  const int bkq = tid & 3;
  const float* Brow = Whh + (size_t)(bni * 64 + brow) * Hz;

  // ldmatrix lane addressing
  const int rowL = lane & 15;
  const int kL = (lane >> 4) * 4;
  const uint32_t aHS =
      smem_u32(Ah) + ((uint32_t)((wm * 16 + rowL) * 68 + kL)) * 4;
  const uint32_t aLS =
      smem_u32(Al) + ((uint32_t)((wm * 16 + rowL) * 68 + kL)) * 4;
  const uint32_t bHS =
      smem_u32(Bh) + ((uint32_t)((wn * 16 + rowL) * 68 + kL)) * 4;
  const uint32_t bLS =
      smem_u32(Bl) + ((uint32_t)((wn * 16 + rowL) * 68 + kL)) * 4;

  for (int g = 0; g < NGROUP; ++g) {
    const float* Arow =
        (g == 0) ? hs + (size_t)m_abs_l * Hz
                 : out + ((size_t)bl_ * Sz + (4 * g + dl - 4)) * Hz;

    // 3 independent chains per ntile
    float chh[2][4], clh[2][4], chl[2][4];
#pragma unroll
    for (int nt = 0; nt < 2; ++nt)
#pragma unroll
      for (int e = 0; e < 4; ++e) {
        chh[nt][e] = 0.f;
        clh[nt][e] = 0.f;
        chl[nt][e] = 0.f;
      }

    float4 pa[2], pb[4];
    pa[0] = *reinterpret_cast<const float4*>(Arow + akq * 4);
    pa[1] = *reinterpret_cast<const float4*>(Arow + (akq + 8) * 4);
#pragma unroll
    for (int j = 0; j < 4; ++j)
      pb[j] = *reinterpret_cast<const float4*>(Brow + (bkq + 4 * j) * 4);

    const int NCH = Hz / 64;  // 16
    for (int ch = 0; ch < NCH; ++ch) {
      {
        uint4 h, l;
        split4(pa[0], h, l);
        *reinterpret_cast<uint4*>(&Ah[arow][akq * 4]) = h;
        *reinterpret_cast<uint4*>(&Al[arow][akq * 4]) = l;
        split4(pa[1], h, l);
        *reinterpret_cast<uint4*>(&Ah[arow][(akq + 8) * 4]) = h;
        *reinterpret_cast<uint4*>(&Al[arow][(akq + 8) * 4]) = l;
#pragma unroll
        for (int j = 0; j < 4; ++j) {
          split4(pb[j], h, l);
          *reinterpret_cast<uint4*>(&Bh[brow][(bkq + 4 * j) * 4]) = h;
          *reinterpret_cast<uint4*>(&Bl[brow][(bkq + 4 * j) * 4]) = l;
        }
      }
      __syncthreads();

      if (ch + 1 < NCH) {
        const int ko = (ch + 1) * 64;
        pa[0] = *reinterpret_cast<const float4*>(Arow + ko + akq * 4);
        pa[1] = *reinterpret_cast<const float4*>(Arow + ko + (akq + 8) * 4);
#pragma unroll
        for (int j = 0; j < 4; ++j)
          pb[j] =
              *reinterpret_cast<const float4*>(Brow + ko + (bkq + 4 * j) * 4);
      }

#pragma unroll
      for (int ks = 0; ks < 8; ++ks) {
        const uint32_t kb = ks * 32;  // 8 floats = 32B
        uint32_t ah0, ah1, ah2, ah3, al0, al1, al2, al3;
        ldsm4(ah0, ah1, ah2, ah3, aHS + kb);
        ldsm4(al0, al1, al2, al3, aLS + kb);
        uint32_t bh0, bh1, bh2, bh3, bl0, bl1, bl2, bl3;
        ldsm4(bh0, bh1, bh2, bh3, bHS + kb);
        ldsm4(bl0, bl1, bl2, bl3, bLS + kb);

        // 6 independent accumulation chains (no serial 3-pass)
        mma_tf32(chh[0], ah0, ah1, ah2, ah3, bh0, bh2);
        mma_tf32(chh[1], ah0, ah1, ah2, ah3, bh1, bh3);
        mma_tf32(clh[0], al0, al1, al2, al3, bh0, bh2);
        mma_tf32(clh[1], al0, al1, al2, al3, bh1, bh3);
        mma_tf32(chl[0], ah0, ah1, ah2, ah3, bl0, bl2);
        mma_tf32(chl[1], ah0, ah1, ah2, ah3, bl1, bl3);
      }
      __syncthreads();
    }

    // epilogue: tanh(pre + sum of chains) -> out (+ h_final on last group)
#pragma unroll
    for (int nt = 0; nt < 2; ++nt) {
      const int n = bni * 64 + wn * 16 + nt * 8 + 2 * tig;
#pragma unroll
      for (int half = 0; half < 2; ++half) {
        const int m_abs = bmi * 32 + wm * 16 + gid + half * 8;
        const int d = m_abs >> 6;
        const int b = m_abs & 63;
        const size_t base = ((size_t)b * Sz + (4 * g + d)) * Hz + n;
        float2 pv = *reinterpret_cast<const float2*>(&g_pre[base]);
        const int e = half * 2;
        float sx = chh[nt][e] + (clh[nt][e] + chl[nt][e]);
        float sy = chh[nt][e + 1] + (clh[nt][e + 1] + chl[nt][e + 1]);
        float2 ov = make_float2(tanhf(pv.x + sx), tanhf(pv.y + sy));
        *reinterpret_cast<float2*>(&out[base]) = ov;
        if (g == NGROUP - 1) {
          *reinterpret_cast<float2*>(&hf[((size_t)d * Bz + b) * Hz + n]) = ov;
        }
      }
    }
    grid_barrier();
  }
}

extern "C" void kernel_launch(void* const* d_in, const int* in_sizes, int n_in,
                              void* d_out, int out_size) {
  (void)in_sizes;
  (void)n_in;
  (void)out_size;
  const float* X = (const float*)d_in[0];    // [B,S,I]
  const float* hs = (const float*)d_in[1];   // [4,B,H]
  const float* Wih = (const float*)d_in[2];  // [H,I]
  const float* Whh = (const float*)d_in[3];  // [H,H]
  const float* bih = (const float*)d_in[4];  // [H]
  const float* bhh = (const float*)d_in[5];  // [H]

  float* out = (float*)d_out;              // [B,S,H]
  float* hf = out + (size_t)Bz * Sz * Hz;  // [4,B,H]

  pre_gemm_mma<<<dim3(Hz / 128, (Bz * Sz) / 128), 256>>>(X, Wih, bih, bhh);

  rnn_persistent_mma<<<NBLK, 256>>>(hs, Whh, out, hf);
}